// round 6
// baseline (speedup 1.0000x reference)
#include <cuda_runtime.h>
#include <math.h>
#include <stdint.h>

// x: [2, 2048, 768]; heads=12, head_dim=64, mlp=3072
#define ROWS   4096
#define CDIM   768
#define QKVDIM 2304
#define HID    3072
#define NHEAD  12
#define HDIM   64
#define SEQ    2048

// ---------------- scratch ----------------
__device__ float g_h[ROWS * CDIM];
__device__ float g_qkv[ROWS * QKVDIM];
__device__ float g_attn[ROWS * CDIM];
__device__ float g_x1[ROWS * CDIM];
__device__ float g_fc1[ROWS * HID];
__device__ float g_vt[24 * HDIM * SEQ];   // transposed V: [z][d][seq]

// ---------------- LayerNorm ----------------
__global__ void ln_kernel(const float* __restrict__ x, const float* __restrict__ gam,
                          const float* __restrict__ bet, float* __restrict__ out) {
    __shared__ float red[8];
    const int t = threadIdx.x;
    const float* xr = x + (size_t)blockIdx.x * CDIM;
    float* orow = out + (size_t)blockIdx.x * CDIM;

    float v0 = xr[t], v1 = xr[t + 256], v2 = xr[t + 512];

    float s = v0 + v1 + v2;
#pragma unroll
    for (int o = 16; o; o >>= 1) s += __shfl_xor_sync(~0u, s, o);
    if ((t & 31) == 0) red[t >> 5] = s;
    __syncthreads();
    s = red[0] + red[1] + red[2] + red[3] + red[4] + red[5] + red[6] + red[7];
    const float mu = s * (1.0f / CDIM);
    __syncthreads();

    float d0 = v0 - mu, d1 = v1 - mu, d2 = v2 - mu;
    float q = d0 * d0 + d1 * d1 + d2 * d2;
#pragma unroll
    for (int o = 16; o; o >>= 1) q += __shfl_xor_sync(~0u, q, o);
    if ((t & 31) == 0) red[t >> 5] = q;
    __syncthreads();
    q = red[0] + red[1] + red[2] + red[3] + red[4] + red[5] + red[6] + red[7];
    const float rs = rsqrtf(q * (1.0f / CDIM) + 1e-5f);

    orow[t]       = d0 * rs * gam[t]       + bet[t];
    orow[t + 256] = d1 * rs * gam[t + 256] + bet[t + 256];
    orow[t + 512] = d2 * rs * gam[t + 512] + bet[t + 512];
}

// ---------------- V transpose ----------------
__global__ void transpose_v(const float* __restrict__ qkv, float* __restrict__ vt) {
    __shared__ float tile[32][33];
    const int z = blockIdx.z, b = z / NHEAD, h = z % NHEAD;
    const float* V = qkv + (size_t)b * SEQ * QKVDIM + 2 * CDIM + h * HDIM;
    float* O = vt + (size_t)z * HDIM * SEQ;
    const int k0 = blockIdx.x << 5, n0 = blockIdx.y << 5;
    const int tx = threadIdx.x, ty = threadIdx.y;
#pragma unroll
    for (int i = 0; i < 32; i += 8)
        tile[ty + i][tx] = V[(size_t)(k0 + ty + i) * QKVDIM + n0 + tx];
    __syncthreads();
#pragma unroll
    for (int i = 0; i < 32; i += 8)
        O[(size_t)(n0 + ty + i) * SEQ + k0 + tx] = tile[tx][ty + i];
}

// ---------------- common helpers ----------------
__device__ __forceinline__ void cp16(uint32_t dst, const void* src) {
    asm volatile("cp.async.cg.shared.global [%0], [%1], 16;\n" :: "r"(dst), "l"(src));
}
__device__ __forceinline__ void cp_commit() { asm volatile("cp.async.commit_group;\n"); }

__device__ __forceinline__ void mma8(float* c, const uint32_t* a, const uint32_t* b) {
    asm volatile(
        "mma.sync.aligned.m16n8k8.row.col.f32.tf32.tf32.f32 "
        "{%0,%1,%2,%3}, {%4,%5,%6,%7}, {%8,%9}, {%0,%1,%2,%3};"
        : "+f"(c[0]), "+f"(c[1]), "+f"(c[2]), "+f"(c[3])
        : "r"(a[0]), "r"(a[1]), "r"(a[2]), "r"(a[3]), "r"(b[0]), "r"(b[1]));
}

// swizzled float index within a [rows][32] panel: 16B word c stored at c^(row&7)
__device__ __forceinline__ int swz(int row, int c) {
    return (row << 5) + (((c ^ (row & 7))) << 2);
}

// ---------------- fused flash attention ----------------
// grid: (16 q-tiles, 24 heads), 256 threads, 2 CTAs/SM. Q tile 128, KV tiles 32.
// smem floats: Q[2p][128][32] @0 | K[2buf][2p][32][32] @8192 | Vt[2buf][64][32] @12288 | P[128][32] @16384
__global__ void __launch_bounds__(256, 2)
flash_attn(const float* __restrict__ qkv, const float* __restrict__ vt,
           float* __restrict__ attn) {
    extern __shared__ float fsm[];
    const uint32_t sb = (uint32_t)__cvta_generic_to_shared(fsm);

    const int t = threadIdx.x, lane = t & 31, warp = t >> 5;
    const int lr = lane >> 2, lc = lane & 3;
    const int z = blockIdx.y, b = z / NHEAD, h = z % NHEAD;
    const int m0 = blockIdx.x * 128;

    const float* Qg = qkv + (size_t)b * SEQ * QKVDIM + h * HDIM;
    const float* Kg = qkv + (size_t)b * SEQ * QKVDIM + CDIM + h * HDIM;
    const float* Vg = vt + (size_t)z * HDIM * SEQ;

    // stage Q (2 panels of [128][32])
#pragma unroll
    for (int i = 0; i < 8; i++) {
        const int idx = t + i * 256;
        const int p = idx >> 10, w = idx & 1023;
        const int row = w >> 3, c = w & 7;
        cp16(sb + (uint32_t)(p * 4096 + swz(row, c)) * 4u,
             Qg + (size_t)(m0 + row) * QKVDIM + p * 32 + c * 4);
    }
    auto stage_kv = [&](int j) {
        const int buf = j & 1;
        const int n0 = j * 32;
        // K tile: 2 panels x [32][32]
#pragma unroll
        for (int i = 0; i < 2; i++) {
            const int idx = t + i * 256;
            const int p = idx >> 8, w = idx & 255;
            const int row = w >> 3, c = w & 7;
            cp16(sb + (uint32_t)(8192 + buf * 2048 + p * 1024 + swz(row, c)) * 4u,
                 Kg + (size_t)(n0 + row) * QKVDIM + p * 32 + c * 4);
        }
        // V tile: 1 panel [64][32]
#pragma unroll
        for (int i = 0; i < 2; i++) {
            const int idx = t + i * 256;
            const int row = idx >> 3, c = idx & 7;
            cp16(sb + (uint32_t)(12288 + buf * 2048 + swz(row, c)) * 4u,
                 Vg + (size_t)row * SEQ + n0 + c * 4);
        }
        cp_commit();
    };
    stage_kv(0);   // group 0 = Q + K0 + V0

    float accO[8][4] = {};
    float m_lo = -1e30f, m_hi = -1e30f, l_lo = 0.f, l_hi = 0.f;
    const int r0 = warp * 16 + lr;
    float* P = fsm + 16384;

    for (int j = 0; j < SEQ / 32; j++) {
        asm volatile("cp.async.wait_group 0;\n" ::: "memory");
        __syncthreads();
        if (j + 1 < SEQ / 32) stage_kv(j + 1);

        // ---- S = Q K^T (128 x 32 tile) ----
        float s[4][4] = {};
        const float* kbase = fsm + 8192 + (j & 1) * 2048;
#pragma unroll
        for (int pp = 0; pp < 2; pp++) {
            const uint32_t* qp = (const uint32_t*)(fsm + pp * 4096);
            const uint32_t* kp = (const uint32_t*)(kbase + pp * 1024);
#pragma unroll
            for (int ks = 0; ks < 4; ks++) {
                uint32_t af[4];
                af[0] = qp[swz(r0,     2 * ks)     + lc];
                af[1] = qp[swz(r0 + 8, 2 * ks)     + lc];
                af[2] = qp[swz(r0,     2 * ks + 1) + lc];
                af[3] = qp[swz(r0 + 8, 2 * ks + 1) + lc];
#pragma unroll
                for (int nf = 0; nf < 4; nf++) {
                    uint32_t bf[2];
                    bf[0] = kp[swz(8 * nf + lr, 2 * ks)     + lc];
                    bf[1] = kp[swz(8 * nf + lr, 2 * ks + 1) + lc];
                    mma8(s[nf], af, bf);
                }
            }
        }

        // ---- online softmax (rows owned per-warp; reduce over lane quad) ----
        float mx_lo = -1e30f, mx_hi = -1e30f;
#pragma unroll
        for (int nf = 0; nf < 4; nf++) {
#pragma unroll
            for (int k4 = 0; k4 < 4; k4++) s[nf][k4] *= 0.125f;
            mx_lo = fmaxf(mx_lo, fmaxf(s[nf][0], s[nf][1]));
            mx_hi = fmaxf(mx_hi, fmaxf(s[nf][2], s[nf][3]));
        }
        mx_lo = fmaxf(mx_lo, __shfl_xor_sync(~0u, mx_lo, 1));
        mx_lo = fmaxf(mx_lo, __shfl_xor_sync(~0u, mx_lo, 2));
        mx_hi = fmaxf(mx_hi, __shfl_xor_sync(~0u, mx_hi, 1));
        mx_hi = fmaxf(mx_hi, __shfl_xor_sync(~0u, mx_hi, 2));
        const float mn_lo = fmaxf(m_lo, mx_lo), mn_hi = fmaxf(m_hi, mx_hi);
        const float al = __expf(m_lo - mn_lo), ah = __expf(m_hi - mn_hi);
        m_lo = mn_lo; m_hi = mn_hi;

        float rs_lo = 0.f, rs_hi = 0.f;
#pragma unroll
        for (int nf = 0; nf < 4; nf++) {
            s[nf][0] = __expf(s[nf][0] - m_lo);
            s[nf][1] = __expf(s[nf][1] - m_lo);
            s[nf][2] = __expf(s[nf][2] - m_hi);
            s[nf][3] = __expf(s[nf][3] - m_hi);
            rs_lo += s[nf][0] + s[nf][1];
            rs_hi += s[nf][2] + s[nf][3];
        }
        rs_lo += __shfl_xor_sync(~0u, rs_lo, 1);
        rs_lo += __shfl_xor_sync(~0u, rs_lo, 2);
        rs_hi += __shfl_xor_sync(~0u, rs_hi, 1);
        rs_hi += __shfl_xor_sync(~0u, rs_hi, 2);
        l_lo = l_lo * al + rs_lo;
        l_hi = l_hi * ah + rs_hi;
#pragma unroll
        for (int nf = 0; nf < 4; nf++) {
            accO[2*nf][0] = accO[2*nf][0]; // keep layout clarity (no-op)
        }
#pragma unroll
        for (int nf = 0; nf < 8; nf++) {
            accO[nf][0] *= al; accO[nf][1] *= al;
            accO[nf][2] *= ah; accO[nf][3] *= ah;
        }

        // ---- store P tile (each warp writes/reads only its own rows) ----
#pragma unroll
        for (int nf = 0; nf < 4; nf++) {
            const int w0 = 2 * nf + (lc >> 1);
            const int sub = (2 * lc) & 3;
            float* d1 = P + (r0 << 5) + (((w0 ^ (r0 & 7))) << 2) + sub;
            *(float2*)d1 = make_float2(s[nf][0], s[nf][1]);
            const int r2 = r0 + 8;
            float* d2 = P + (r2 << 5) + (((w0 ^ (r2 & 7))) << 2) + sub;
            *(float2*)d2 = make_float2(s[nf][2], s[nf][3]);
        }
        __syncwarp();

        // ---- O += P V ----
        const float* vbase = fsm + 12288 + (j & 1) * 2048;
        const uint32_t* ap = (const uint32_t*)P;
        const uint32_t* vp = (const uint32_t*)vbase;
#pragma unroll
        for (int ks = 0; ks < 4; ks++) {
            uint32_t af[4];
            af[0] = ap[swz(r0,     2 * ks)     + lc];
            af[1] = ap[swz(r0 + 8, 2 * ks)     + lc];
            af[2] = ap[swz(r0,     2 * ks + 1) + lc];
            af[3] = ap[swz(r0 + 8, 2 * ks + 1) + lc];
#pragma unroll
            for (int nf = 0; nf < 8; nf++) {
                uint32_t bf[2];
                bf[0] = vp[swz(8 * nf + lr, 2 * ks)     + lc];
                bf[1] = vp[swz(8 * nf + lr, 2 * ks + 1) + lc];
                mma8(accO[nf], af, bf);
            }
        }
    }

    // ---- epilogue ----
    const float inv_lo = 1.0f / l_lo, inv_hi = 1.0f / l_hi;
    float* Cb = attn + (size_t)b * SEQ * CDIM + h * HDIM;
    const int m = m0 + r0;
#pragma unroll
    for (int nf = 0; nf < 8; nf++) {
        const int n = 8 * nf + 2 * lc;
        *(float2*)(Cb + (size_t)m * CDIM + n) =
            make_float2(accO[nf][0] * inv_lo, accO[nf][1] * inv_lo);
        *(float2*)(Cb + (size_t)(m + 8) * CDIM + n) =
            make_float2(accO[nf][2] * inv_hi, accO[nf][3] * inv_hi);
    }
}

// ---------------- TF32 tensor-core NT GEMM, 3-stage cp.async, 1 sync/iter ----------------
template <int EPI, int WARP_M, int WARP_N, int WM_T, int WN_T>
__global__ void __launch_bounds__(WARP_M * WARP_N * 32, 2)
gemm_tc(const float* __restrict__ A, int lda,
        const float* __restrict__ B, int ldb,
        float* __restrict__ C, int ldc, int K,
        const float* __restrict__ bias,
        const float* __restrict__ res) {
    constexpr int NT = WARP_M * WARP_N * 32;
    constexpr int BM = WARP_M * WM_T * 16;
    constexpr int BN = WARP_N * WN_T * 8;
    constexpr int ASZ = BM * 32;
    constexpr int BSZ = BN * 32;
    constexpr int STG = ASZ + BSZ;
    constexpr int NA = ASZ / 4 / NT;
    constexpr int NB = BSZ / 4 / NT;

    extern __shared__ uint32_t smem[];
    const uint32_t smem_b = (uint32_t)__cvta_generic_to_shared(smem);

    const int m0 = blockIdx.y * BM;
    const int n0 = blockIdx.x * BN;
    const int t = threadIdx.x;
    const int lane = t & 31, warp = t >> 5;
    const int wm = warp / WARP_N, wn = warp % WARP_N;
    const int lr = lane >> 2, lc = lane & 3;

    const float* Abase = A + (size_t)m0 * lda;
    const float* Bbase = B + (size_t)n0 * ldb;

    auto issue = [&](int j) {
        const int st = (j % 3) * STG;
        const float* Ak = Abase + j * 32;
        const uint32_t sa = smem_b + (uint32_t)st * 4u;
#pragma unroll
        for (int i = 0; i < NA; i++) {
            const int idx = t + i * NT;
            const int row = idx >> 3, c = idx & 7;
            cp16(sa + (uint32_t)swz(row, c) * 4u, Ak + (size_t)row * lda + c * 4);
        }
        const float* Bk = Bbase + j * 32;
        const uint32_t sbp = smem_b + (uint32_t)(st + ASZ) * 4u;
#pragma unroll
        for (int i = 0; i < NB; i++) {
            const int idx = t + i * NT;
            const int row = idx >> 3, c = idx & 7;
            cp16(sbp + (uint32_t)swz(row, c) * 4u, Bk + (size_t)row * ldb + c * 4);
        }
        cp_commit();
    };

    const int T = K >> 5;
    issue(0);
    issue(1);

    float acc[WM_T][WN_T][4] = {};

    for (int j = 0; j < T; j++) {
        asm volatile("cp.async.wait_group 1;\n" ::: "memory");
        __syncthreads();
        const uint32_t* a = smem + (j % 3) * STG;
        const uint32_t* b = a + ASZ;

#pragma unroll
        for (int ks = 0; ks < 4; ks++) {
            uint32_t af[WM_T][4], bf[WN_T][2];
#pragma unroll
            for (int mt = 0; mt < WM_T; mt++) {
                const int row = (wm * WM_T + mt) * 16 + lr;
                af[mt][0] = a[swz(row,     2 * ks)     + lc];
                af[mt][1] = a[swz(row + 8, 2 * ks)     + lc];
                af[mt][2] = a[swz(row,     2 * ks + 1) + lc];
                af[mt][3] = a[swz(row + 8, 2 * ks + 1) + lc];
            }
#pragma unroll
            for (int nf = 0; nf < WN_T; nf++) {
                const int row = (wn * WN_T + nf) * 8 + lr;
                bf[nf][0] = b[swz(row, 2 * ks)     + lc];
                bf[nf][1] = b[swz(row, 2 * ks + 1) + lc];
            }
#pragma unroll
            for (int mt = 0; mt < WM_T; mt++)
#pragma unroll
                for (int nf = 0; nf < WN_T; nf++)
                    mma8(acc[mt][nf], af[mt], bf[nf]);
        }
        if (j + 2 < T) issue(j + 2);
        else cp_commit();   // keep group counts aligned with wait_group 1
    }

#pragma unroll
    for (int mi = 0; mi < WM_T; mi++) {
        const int m = m0 + (wm * WM_T + mi) * 16 + lr;
#pragma unroll
        for (int ni = 0; ni < WN_T; ni++) {
            const int n = n0 + (wn * WN_T + ni) * 8 + (lc << 1);
            float2 bb = make_float2(0.f, 0.f);
            if (EPI != 0) bb = *(const float2*)(bias + n);
#pragma unroll
            for (int half = 0; half < 2; half++) {
                const int mm = m + half * 8;
                float v0 = acc[mi][ni][half * 2 + 0];
                float v1 = acc[mi][ni][half * 2 + 1];
                if (EPI != 0) { v0 += bb.x; v1 += bb.y; }
                if (EPI == 2) {
                    float2 r2 = *(const float2*)(res + (size_t)mm * ldc + n);
                    v0 += r2.x; v1 += r2.y;
                }
                if (EPI == 3) {
                    v0 = 0.5f * v0 * (1.0f + erff(v0 * 0.70710678118654752f));
                    v1 = 0.5f * v1 * (1.0f + erff(v1 * 0.70710678118654752f));
                }
                *(float2*)(C + (size_t)mm * ldc + n) = make_float2(v0, v1);
            }
        }
    }
}

// ---------------- launch ----------------
extern "C" void kernel_launch(void* const* d_in, const int* in_sizes, int n_in,
                              void* d_out, int out_size) {
    const float* x      = (const float*)d_in[0];
    const float* ln1_g  = (const float*)d_in[1];
    const float* ln1_b  = (const float*)d_in[2];
    const float* qkv_w  = (const float*)d_in[3];
    const float* proj_w = (const float*)d_in[4];
    const float* proj_b = (const float*)d_in[5];
    const float* ln2_g  = (const float*)d_in[6];
    const float* ln2_b  = (const float*)d_in[7];
    const float* fc1_w  = (const float*)d_in[8];
    const float* fc1_b  = (const float*)d_in[9];
    const float* fc2_w  = (const float*)d_in[10];
    const float* fc2_b  = (const float*)d_in[11];
    float* out = (float*)d_out;

    float *h, *qkv, *attn, *x1, *fc1, *vt;
    cudaGetSymbolAddress((void**)&h, g_h);
    cudaGetSymbolAddress((void**)&qkv, g_qkv);
    cudaGetSymbolAddress((void**)&attn, g_attn);
    cudaGetSymbolAddress((void**)&x1, g_x1);
    cudaGetSymbolAddress((void**)&fc1, g_fc1);
    cudaGetSymbolAddress((void**)&vt, g_vt);

    constexpr int SM128 = 3 * (128 * 32 + 128 * 32) * 4;  // 96KB (3 stages)
    constexpr int SMFA  = 20480 * 4;                       // 80KB
    cudaFuncSetAttribute(gemm_tc<0, 2, 4, 4, 4>, cudaFuncAttributeMaxDynamicSharedMemorySize, SM128);
    cudaFuncSetAttribute(gemm_tc<2, 2, 4, 4, 4>, cudaFuncAttributeMaxDynamicSharedMemorySize, SM128);
    cudaFuncSetAttribute(gemm_tc<3, 2, 4, 4, 4>, cudaFuncAttributeMaxDynamicSharedMemorySize, SM128);
    cudaFuncSetAttribute(flash_attn, cudaFuncAttributeMaxDynamicSharedMemorySize, SMFA);

    // 1) LN1
    ln_kernel<<<ROWS, 256>>>(x, ln1_g, ln1_b, h);

    // 2) QKV
    gemm_tc<0, 2, 4, 4, 4><<<dim3(QKVDIM / 128, ROWS / 128, 1), 256, SM128>>>(
        h, CDIM, qkv_w, CDIM, qkv, QKVDIM, CDIM, nullptr, nullptr);

    // 3) V transpose + fused flash attention
    transpose_v<<<dim3(SEQ / 32, HDIM / 32, 24), dim3(32, 8)>>>(qkv, vt);
    flash_attn<<<dim3(SEQ / 128, 24), 256, SMFA>>>(qkv, vt, attn);

    // 4) x1 = x + attn @ proj_w^T + proj_b
    gemm_tc<2, 2, 4, 4, 4><<<dim3(CDIM / 128, ROWS / 128, 1), 256, SM128>>>(
        attn, CDIM, proj_w, CDIM, x1, CDIM, CDIM, proj_b, x);

    // 5) LN2
    ln_kernel<<<ROWS, 256>>>(x1, ln2_g, ln2_b, h);

    // 6) fc1 + exact GELU
    gemm_tc<3, 2, 4, 4, 4><<<dim3(HID / 128, ROWS / 128, 1), 256, SM128>>>(
        h, CDIM, fc1_w, CDIM, fc1, HID, CDIM, fc1_b, nullptr);

    // 7) out = x1 + fc1 @ fc2_w^T + fc2_b
    gemm_tc<2, 2, 4, 4, 4><<<dim3(CDIM / 128, ROWS / 128, 1), 256, SM128>>>(
        fc1, HID, fc2_w, HID, out, CDIM, HID, fc2_b, x1);
}

// round 7
// speedup vs baseline: 1.0193x; 1.0193x over previous
#include <cuda_runtime.h>
#include <math.h>
#include <stdint.h>

// x: [2, 2048, 768]; heads=12, head_dim=64, mlp=3072
#define ROWS   4096
#define CDIM   768
#define QKVDIM 2304
#define HID    3072
#define NHEAD  12
#define HDIM   64
#define SEQ    2048

// ---------------- scratch ----------------
__device__ float g_h[ROWS * CDIM];
__device__ float g_qkv[ROWS * QKVDIM];
__device__ float g_attn[ROWS * CDIM];
__device__ float g_x1[ROWS * CDIM];
__device__ float g_fc1[ROWS * HID];
__device__ float2 g_pk[24 * 32 * 2048];   // packed K fragments: [z][tile][frag64][lane32]
__device__ float2 g_pv[24 * 32 * 2048];   // packed V fragments

// ---------------- LayerNorm ----------------
__global__ void ln_kernel(const float* __restrict__ x, const float* __restrict__ gam,
                          const float* __restrict__ bet, float* __restrict__ out) {
    __shared__ float red[8];
    const int t = threadIdx.x;
    const float* xr = x + (size_t)blockIdx.x * CDIM;
    float* orow = out + (size_t)blockIdx.x * CDIM;

    float v0 = xr[t], v1 = xr[t + 256], v2 = xr[t + 512];

    float s = v0 + v1 + v2;
#pragma unroll
    for (int o = 16; o; o >>= 1) s += __shfl_xor_sync(~0u, s, o);
    if ((t & 31) == 0) red[t >> 5] = s;
    __syncthreads();
    s = red[0] + red[1] + red[2] + red[3] + red[4] + red[5] + red[6] + red[7];
    const float mu = s * (1.0f / CDIM);
    __syncthreads();

    float d0 = v0 - mu, d1 = v1 - mu, d2 = v2 - mu;
    float q = d0 * d0 + d1 * d1 + d2 * d2;
#pragma unroll
    for (int o = 16; o; o >>= 1) q += __shfl_xor_sync(~0u, q, o);
    if ((t & 31) == 0) red[t >> 5] = q;
    __syncthreads();
    q = red[0] + red[1] + red[2] + red[3] + red[4] + red[5] + red[6] + red[7];
    const float rs = rsqrtf(q * (1.0f / CDIM) + 1e-5f);

    orow[t]       = d0 * rs * gam[t]       + bet[t];
    orow[t + 256] = d1 * rs * gam[t + 256] + bet[t + 256];
    orow[t + 512] = d2 * rs * gam[t + 512] + bet[t + 512];
}

// ---------------- pack K,V into mma fragment layout ----------------
// frag f = nf*8+ks (nf: 8-row group, ks: 8-col k-slice), lane (lr=lane>>2, lc=lane&3):
//   K: (K[j*64+8nf+lr][8ks+lc], K[...][8ks+lc+4])
//   V: (V[j*64+8ks+lc][8nf+lr], V[j*64+8ks+lc+4][8nf+lr])   (B-side of O = P @ V)
__global__ void pack_kv(const float* __restrict__ qkv,
                        float2* __restrict__ pk, float2* __restrict__ pv) {
    const int z = blockIdx.y, j = blockIdx.x, b = z / NHEAD, h = z % NHEAD;
    const int t = threadIdx.x;
    const float* kb = qkv + (size_t)b * SEQ * QKVDIM + CDIM + h * HDIM;
    const float* vb = qkv + (size_t)b * SEQ * QKVDIM + 2 * CDIM + h * HDIM;
    float2* pkt = pk + ((size_t)z * 32 + j) * 2048;
    float2* pvt = pv + ((size_t)z * 32 + j) * 2048;
#pragma unroll
    for (int i = 0; i < 8; i++) {
        const int it = t + i * 256;
        const int f = it >> 5, lane = it & 31;
        const int nf = f >> 3, ks = f & 7, lr = lane >> 2, lc = lane & 3;
        const float* p = kb + (size_t)(j * 64 + nf * 8 + lr) * QKVDIM + ks * 8 + lc;
        pkt[it] = make_float2(p[0], p[4]);
        const float* q = vb + (size_t)(j * 64 + ks * 8 + lc) * QKVDIM + nf * 8 + lr;
        pvt[it] = make_float2(q[0], q[4 * QKVDIM]);
    }
}

// ---------------- common helpers ----------------
__device__ __forceinline__ void cp16(uint32_t dst, const void* src) {
    asm volatile("cp.async.cg.shared.global [%0], [%1], 16;\n" :: "r"(dst), "l"(src));
}
__device__ __forceinline__ void cp_commit() { asm volatile("cp.async.commit_group;\n"); }

__device__ __forceinline__ void mma8(float* c, const uint32_t* a, const uint32_t* b) {
    asm volatile(
        "mma.sync.aligned.m16n8k8.row.col.f32.tf32.tf32.f32 "
        "{%0,%1,%2,%3}, {%4,%5,%6,%7}, {%8,%9}, {%0,%1,%2,%3};"
        : "+f"(c[0]), "+f"(c[1]), "+f"(c[2]), "+f"(c[3])
        : "r"(a[0]), "r"(a[1]), "r"(a[2]), "r"(a[3]), "r"(b[0]), "r"(b[1]));
}

// swizzled float index within a [rows][32] panel: 16B word c stored at c^(row&7)
__device__ __forceinline__ int swz(int row, int c) {
    return (row << 5) + (((c ^ (row & 7))) << 2);
}

// ---------------- fused flash attention (Q in regs, packed KV) ----------------
// grid: (16 q-tiles, 24 heads), 256 threads. KV tiles of 64.
// smem floats: P/Qstage [2p][128][32] @0 | Kp[2buf][4096] @8192 | Vp[2buf][4096] @16384
__global__ void __launch_bounds__(256, 1)
flash_attn(const float* __restrict__ qkv, const float2* __restrict__ pk,
           const float2* __restrict__ pv, float* __restrict__ attn) {
    extern __shared__ float fsm[];
    const uint32_t sb = (uint32_t)__cvta_generic_to_shared(fsm);

    const int t = threadIdx.x, lane = t & 31, warp = t >> 5;
    const int lr = lane >> 2, lc = lane & 3;
    const int z = blockIdx.y, b = z / NHEAD, h = z % NHEAD;
    const int m0 = blockIdx.x * 128;

    const float* Qg = qkv + (size_t)b * SEQ * QKVDIM + h * HDIM;
    const float2* pkz = pk + (size_t)z * 32 * 2048;
    const float2* pvz = pv + (size_t)z * 32 * 2048;

    // stage Q into panels (swizzled), one group
#pragma unroll
    for (int i = 0; i < 8; i++) {
        const int idx = t + i * 256;
        const int p = idx >> 10, w = idx & 1023;
        const int row = w >> 3, c = w & 7;
        cp16(sb + (uint32_t)(p * 4096 + swz(row, c)) * 4u,
             Qg + (size_t)(m0 + row) * QKVDIM + p * 32 + c * 4);
    }
    cp_commit();

    auto stage = [&](int j) {   // linear copy of packed K & V tiles
        const int buf = j & 1;
        const float4* ks = (const float4*)(pkz + (size_t)j * 2048);
        const uint32_t kd = sb + (uint32_t)(8192 + buf * 4096) * 4u;
#pragma unroll
        for (int i = 0; i < 4; i++) cp16(kd + (t + i * 256) * 16, ks + t + i * 256);
        const float4* vs = (const float4*)(pvz + (size_t)j * 2048);
        const uint32_t vd = sb + (uint32_t)(16384 + buf * 4096) * 4u;
#pragma unroll
        for (int i = 0; i < 4; i++) cp16(vd + (t + i * 256) * 16, vs + t + i * 256);
        cp_commit();
    };
    stage(0);

    asm volatile("cp.async.wait_group 0;\n" ::: "memory");
    __syncthreads();

    // Q fragments -> registers (warp reads only its own 16 rows)
    const int r0 = warp * 16 + lr;
    uint32_t qf[8][4];
#pragma unroll
    for (int ks = 0; ks < 8; ks++) {
        const uint32_t* qp = (const uint32_t*)(fsm + (ks >> 2) * 4096);
        const int k2 = (ks & 3) * 2;
        qf[ks][0] = qp[swz(r0,     k2)     + lc];
        qf[ks][1] = qp[swz(r0 + 8, k2)     + lc];
        qf[ks][2] = qp[swz(r0,     k2 + 1) + lc];
        qf[ks][3] = qp[swz(r0 + 8, k2 + 1) + lc];
    }

    float accO[8][4] = {};
    float m_lo = -1e30f, m_hi = -1e30f, l_lo = 0.f, l_hi = 0.f;
    float* P = fsm;   // reuse Q staging region (per-warp rows only)

    for (int j = 0; j < 32; j++) {
        asm volatile("cp.async.wait_group 0;\n" ::: "memory");
        __syncthreads();                 // all warps done with prev compute
        if (j + 1 < 32) stage(j + 1);    // overlaps with compute below

        // ---- S = Q K^T (128x64 tile) ----
        float s[8][4] = {};
        const float2* kp = (const float2*)(fsm + 8192 + (j & 1) * 4096);
#pragma unroll
        for (int ks = 0; ks < 8; ks++) {
#pragma unroll
            for (int nf = 0; nf < 8; nf++) {
                float2 bfv = kp[(nf * 8 + ks) * 32 + lane];
                mma8(s[nf], qf[ks], (const uint32_t*)&bfv);
            }
        }

        // ---- online softmax ----
        float mx_lo = -1e30f, mx_hi = -1e30f;
#pragma unroll
        for (int nf = 0; nf < 8; nf++) {
#pragma unroll
            for (int k4 = 0; k4 < 4; k4++) s[nf][k4] *= 0.125f;
            mx_lo = fmaxf(mx_lo, fmaxf(s[nf][0], s[nf][1]));
            mx_hi = fmaxf(mx_hi, fmaxf(s[nf][2], s[nf][3]));
        }
        mx_lo = fmaxf(mx_lo, __shfl_xor_sync(~0u, mx_lo, 1));
        mx_lo = fmaxf(mx_lo, __shfl_xor_sync(~0u, mx_lo, 2));
        mx_hi = fmaxf(mx_hi, __shfl_xor_sync(~0u, mx_hi, 1));
        mx_hi = fmaxf(mx_hi, __shfl_xor_sync(~0u, mx_hi, 2));
        const float mn_lo = fmaxf(m_lo, mx_lo), mn_hi = fmaxf(m_hi, mx_hi);
        const float al = __expf(m_lo - mn_lo), ah = __expf(m_hi - mn_hi);
        m_lo = mn_lo; m_hi = mn_hi;

        float rs_lo = 0.f, rs_hi = 0.f;
#pragma unroll
        for (int nf = 0; nf < 8; nf++) {
            s[nf][0] = __expf(s[nf][0] - m_lo);
            s[nf][1] = __expf(s[nf][1] - m_lo);
            s[nf][2] = __expf(s[nf][2] - m_hi);
            s[nf][3] = __expf(s[nf][3] - m_hi);
            rs_lo += s[nf][0] + s[nf][1];
            rs_hi += s[nf][2] + s[nf][3];
        }
        rs_lo += __shfl_xor_sync(~0u, rs_lo, 1);
        rs_lo += __shfl_xor_sync(~0u, rs_lo, 2);
        rs_hi += __shfl_xor_sync(~0u, rs_hi, 1);
        rs_hi += __shfl_xor_sync(~0u, rs_hi, 2);
        l_lo = l_lo * al + rs_lo;
        l_hi = l_hi * ah + rs_hi;
#pragma unroll
        for (int nf = 0; nf < 8; nf++) {
            accO[nf][0] *= al; accO[nf][1] *= al;
            accO[nf][2] *= ah; accO[nf][3] *= ah;
        }

        // ---- store P tile (warp-private rows) ----
#pragma unroll
        for (int nf = 0; nf < 8; nf++) {
            const int p = nf >> 2;
            const int w0 = 2 * (nf & 3) + (lc >> 1);
            const int sub = (2 * lc) & 3;
            float* d1 = P + p * 4096 + (r0 << 5) + (((w0 ^ (r0 & 7))) << 2) + sub;
            *(float2*)d1 = make_float2(s[nf][0], s[nf][1]);
            const int r2 = r0 + 8;
            float* d2 = P + p * 4096 + (r2 << 5) + (((w0 ^ (r2 & 7))) << 2) + sub;
            *(float2*)d2 = make_float2(s[nf][2], s[nf][3]);
        }
        __syncwarp();

        // ---- O += P V ----
        const float2* vp = (const float2*)(fsm + 16384 + (j & 1) * 4096);
#pragma unroll
        for (int kk = 0; kk < 8; kk++) {
            const uint32_t* ap = (const uint32_t*)(P + (kk >> 2) * 4096);
            const int k2 = (kk & 3) * 2;
            uint32_t af[4];
            af[0] = ap[swz(r0,     k2)     + lc];
            af[1] = ap[swz(r0 + 8, k2)     + lc];
            af[2] = ap[swz(r0,     k2 + 1) + lc];
            af[3] = ap[swz(r0 + 8, k2 + 1) + lc];
#pragma unroll
            for (int nf = 0; nf < 8; nf++) {
                float2 bfv = vp[(nf * 8 + kk) * 32 + lane];
                mma8(accO[nf], af, (const uint32_t*)&bfv);
            }
        }
    }

    // ---- epilogue ----
    const float inv_lo = 1.0f / l_lo, inv_hi = 1.0f / l_hi;
    float* Cb = attn + (size_t)b * SEQ * CDIM + h * HDIM;
    const int m = m0 + r0;
#pragma unroll
    for (int nf = 0; nf < 8; nf++) {
        const int n = 8 * nf + 2 * lc;
        *(float2*)(Cb + (size_t)m * CDIM + n) =
            make_float2(accO[nf][0] * inv_lo, accO[nf][1] * inv_lo);
        *(float2*)(Cb + (size_t)(m + 8) * CDIM + n) =
            make_float2(accO[nf][2] * inv_hi, accO[nf][3] * inv_hi);
    }
}

// ---------------- TF32 tensor-core NT GEMM, 2-stage cp.async (round-5) ----------------
template <int EPI, int WARP_M, int WARP_N, int WM_T, int WN_T>
__global__ void __launch_bounds__(WARP_M * WARP_N * 32, 2)
gemm_tc(const float* __restrict__ A, int lda,
        const float* __restrict__ B, int ldb,
        float* __restrict__ C, int ldc, int K,
        const float* __restrict__ bias,
        const float* __restrict__ res) {
    constexpr int NT = WARP_M * WARP_N * 32;
    constexpr int BM = WARP_M * WM_T * 16;
    constexpr int BN = WARP_N * WN_T * 8;
    constexpr int ASZ = BM * 32;
    constexpr int BSZ = BN * 32;
    constexpr int STG = ASZ + BSZ;
    constexpr int NA = ASZ / 4 / NT;
    constexpr int NB = BSZ / 4 / NT;

    extern __shared__ uint32_t smem[];
    const uint32_t smem_b = (uint32_t)__cvta_generic_to_shared(smem);

    const int m0 = blockIdx.y * BM;
    const int n0 = blockIdx.x * BN;
    const int t = threadIdx.x;
    const int lane = t & 31, warp = t >> 5;
    const int wm = warp / WARP_N, wn = warp % WARP_N;
    const int lr = lane >> 2, lc = lane & 3;

    const float* Abase = A + (size_t)m0 * lda;
    const float* Bbase = B + (size_t)n0 * ldb;

    auto issue = [&](int j, int buf) {
        const float* Ak = Abase + j * 32;
        const uint32_t sa = smem_b + (uint32_t)(buf * STG) * 4u;
#pragma unroll
        for (int i = 0; i < NA; i++) {
            const int idx = t + i * NT;
            const int row = idx >> 3, c = idx & 7;
            cp16(sa + (uint32_t)swz(row, c) * 4u, Ak + (size_t)row * lda + c * 4);
        }
        const float* Bk = Bbase + j * 32;
        const uint32_t sbp = smem_b + (uint32_t)(buf * STG + ASZ) * 4u;
#pragma unroll
        for (int i = 0; i < NB; i++) {
            const int idx = t + i * NT;
            const int row = idx >> 3, c = idx & 7;
            cp16(sbp + (uint32_t)swz(row, c) * 4u, Bk + (size_t)row * ldb + c * 4);
        }
        cp_commit();
    };

    const int T = K >> 5;
    issue(0, 0);
    issue(1, 1);

    float acc[WM_T][WN_T][4] = {};
    int buf = 0;

    for (int j = 0; j < T; j++) {
        asm volatile("cp.async.wait_group 1;\n" ::: "memory");
        __syncthreads();
        const uint32_t* a = smem + buf * STG;
        const uint32_t* b = a + ASZ;

#pragma unroll
        for (int ks = 0; ks < 4; ks++) {
            uint32_t af[WM_T][4], bf[WN_T][2];
#pragma unroll
            for (int mt = 0; mt < WM_T; mt++) {
                const int row = (wm * WM_T + mt) * 16 + lr;
                af[mt][0] = a[swz(row,     2 * ks)     + lc];
                af[mt][1] = a[swz(row + 8, 2 * ks)     + lc];
                af[mt][2] = a[swz(row,     2 * ks + 1) + lc];
                af[mt][3] = a[swz(row + 8, 2 * ks + 1) + lc];
            }
#pragma unroll
            for (int nf = 0; nf < WN_T; nf++) {
                const int row = (wn * WN_T + nf) * 8 + lr;
                bf[nf][0] = b[swz(row, 2 * ks)     + lc];
                bf[nf][1] = b[swz(row, 2 * ks + 1) + lc];
            }
#pragma unroll
            for (int mt = 0; mt < WM_T; mt++)
#pragma unroll
                for (int nf = 0; nf < WN_T; nf++)
                    mma8(acc[mt][nf], af[mt], bf[nf]);
        }
        __syncthreads();
        if (j + 2 < T) issue(j + 2, buf);
        else cp_commit();
        buf ^= 1;
    }

#pragma unroll
    for (int mi = 0; mi < WM_T; mi++) {
        const int m = m0 + (wm * WM_T + mi) * 16 + lr;
#pragma unroll
        for (int ni = 0; ni < WN_T; ni++) {
            const int n = n0 + (wn * WN_T + ni) * 8 + (lc << 1);
            float2 bb = make_float2(0.f, 0.f);
            if (EPI != 0) bb = *(const float2*)(bias + n);
#pragma unroll
            for (int half = 0; half < 2; half++) {
                const int mm = m + half * 8;
                float v0 = acc[mi][ni][half * 2 + 0];
                float v1 = acc[mi][ni][half * 2 + 1];
                if (EPI != 0) { v0 += bb.x; v1 += bb.y; }
                if (EPI == 2) {
                    float2 r2 = *(const float2*)(res + (size_t)mm * ldc + n);
                    v0 += r2.x; v1 += r2.y;
                }
                if (EPI == 3) {
                    v0 = 0.5f * v0 * (1.0f + erff(v0 * 0.70710678118654752f));
                    v1 = 0.5f * v1 * (1.0f + erff(v1 * 0.70710678118654752f));
                }
                *(float2*)(C + (size_t)mm * ldc + n) = make_float2(v0, v1);
            }
        }
    }
}

// ---------------- launch ----------------
extern "C" void kernel_launch(void* const* d_in, const int* in_sizes, int n_in,
                              void* d_out, int out_size) {
    const float* x      = (const float*)d_in[0];
    const float* ln1_g  = (const float*)d_in[1];
    const float* ln1_b  = (const float*)d_in[2];
    const float* qkv_w  = (const float*)d_in[3];
    const float* proj_w = (const float*)d_in[4];
    const float* proj_b = (const float*)d_in[5];
    const float* ln2_g  = (const float*)d_in[6];
    const float* ln2_b  = (const float*)d_in[7];
    const float* fc1_w  = (const float*)d_in[8];
    const float* fc1_b  = (const float*)d_in[9];
    const float* fc2_w  = (const float*)d_in[10];
    const float* fc2_b  = (const float*)d_in[11];
    float* out = (float*)d_out;

    float *h, *qkv, *attn, *x1, *fc1;
    float2 *pkp, *pvp;
    cudaGetSymbolAddress((void**)&h, g_h);
    cudaGetSymbolAddress((void**)&qkv, g_qkv);
    cudaGetSymbolAddress((void**)&attn, g_attn);
    cudaGetSymbolAddress((void**)&x1, g_x1);
    cudaGetSymbolAddress((void**)&fc1, g_fc1);
    cudaGetSymbolAddress((void**)&pkp, g_pk);
    cudaGetSymbolAddress((void**)&pvp, g_pv);

    constexpr int SM128 = 2 * (128 * 32 + 128 * 32) * 4;  // 64KB
    constexpr int SMFA  = 24576 * 4;                       // 96KB
    cudaFuncSetAttribute(gemm_tc<0, 2, 4, 4, 4>, cudaFuncAttributeMaxDynamicSharedMemorySize, SM128);
    cudaFuncSetAttribute(gemm_tc<2, 2, 4, 4, 4>, cudaFuncAttributeMaxDynamicSharedMemorySize, SM128);
    cudaFuncSetAttribute(gemm_tc<3, 2, 4, 4, 4>, cudaFuncAttributeMaxDynamicSharedMemorySize, SM128);
    cudaFuncSetAttribute(flash_attn, cudaFuncAttributeMaxDynamicSharedMemorySize, SMFA);

    // 1) LN1
    ln_kernel<<<ROWS, 256>>>(x, ln1_g, ln1_b, h);

    // 2) QKV
    gemm_tc<0, 2, 4, 4, 4><<<dim3(QKVDIM / 128, ROWS / 128, 1), 256, SM128>>>(
        h, CDIM, qkv_w, CDIM, qkv, QKVDIM, CDIM, nullptr, nullptr);

    // 3) pack K/V fragments + fused flash attention
    pack_kv<<<dim3(32, 24), 256>>>(qkv, pkp, pvp);
    flash_attn<<<dim3(SEQ / 128, 24), 256, SMFA>>>(qkv, pkp, pvp, attn);

    // 4) x1 = x + attn @ proj_w^T + proj_b
    gemm_tc<2, 2, 4, 4, 4><<<dim3(CDIM / 128, ROWS / 128, 1), 256, SM128>>>(
        attn, CDIM, proj_w, CDIM, x1, CDIM, CDIM, proj_b, x);

    // 5) LN2
    ln_kernel<<<ROWS, 256>>>(x1, ln2_g, ln2_b, h);

    // 6) fc1 + exact GELU
    gemm_tc<3, 2, 4, 4, 4><<<dim3(HID / 128, ROWS / 128, 1), 256, SM128>>>(
        h, CDIM, fc1_w, CDIM, fc1, HID, CDIM, fc1_b, nullptr);

    // 7) out = x1 + fc1 @ fc2_w^T + fc2_b
    gemm_tc<2, 2, 4, 4, 4><<<dim3(CDIM / 128, ROWS / 128, 1), 256, SM128>>>(
        fc1, HID, fc2_w, HID, out, CDIM, HID, fc2_b, x1);
}

// round 8
// speedup vs baseline: 1.0739x; 1.0536x over previous
#include <cuda_runtime.h>
#include <math.h>
#include <stdint.h>

// x: [2, 2048, 768]; heads=12, head_dim=64, mlp=3072
#define ROWS   4096
#define CDIM   768
#define QKVDIM 2304
#define HID    3072
#define NHEAD  12
#define HDIM   64
#define SEQ    2048

// ---------------- scratch ----------------
__device__ float g_h[ROWS * CDIM];
__device__ float g_qkv[ROWS * QKVDIM];
__device__ float g_attn[ROWS * CDIM];
__device__ float g_x1[ROWS * CDIM];
__device__ float g_fc1[ROWS * HID];
__device__ float2 g_pk[24 * 32 * 2048];   // packed K fragments: [z][tile][frag64][lane32]
__device__ float2 g_pv[24 * 32 * 2048];   // packed V fragments

// ---------------- LayerNorm ----------------
__global__ void ln_kernel(const float* __restrict__ x, const float* __restrict__ gam,
                          const float* __restrict__ bet, float* __restrict__ out) {
    __shared__ float red[8];
    const int t = threadIdx.x;
    const float* xr = x + (size_t)blockIdx.x * CDIM;
    float* orow = out + (size_t)blockIdx.x * CDIM;

    float v0 = xr[t], v1 = xr[t + 256], v2 = xr[t + 512];

    float s = v0 + v1 + v2;
#pragma unroll
    for (int o = 16; o; o >>= 1) s += __shfl_xor_sync(~0u, s, o);
    if ((t & 31) == 0) red[t >> 5] = s;
    __syncthreads();
    s = red[0] + red[1] + red[2] + red[3] + red[4] + red[5] + red[6] + red[7];
    const float mu = s * (1.0f / CDIM);
    __syncthreads();

    float d0 = v0 - mu, d1 = v1 - mu, d2 = v2 - mu;
    float q = d0 * d0 + d1 * d1 + d2 * d2;
#pragma unroll
    for (int o = 16; o; o >>= 1) q += __shfl_xor_sync(~0u, q, o);
    if ((t & 31) == 0) red[t >> 5] = q;
    __syncthreads();
    q = red[0] + red[1] + red[2] + red[3] + red[4] + red[5] + red[6] + red[7];
    const float rs = rsqrtf(q * (1.0f / CDIM) + 1e-5f);

    orow[t]       = d0 * rs * gam[t]       + bet[t];
    orow[t + 256] = d1 * rs * gam[t + 256] + bet[t + 256];
    orow[t + 512] = d2 * rs * gam[t + 512] + bet[t + 512];
}

// ---------------- pack K,V into mma fragment layout ----------------
__global__ void pack_kv(const float* __restrict__ qkv,
                        float2* __restrict__ pk, float2* __restrict__ pv) {
    const int z = blockIdx.y, j = blockIdx.x, b = z / NHEAD, h = z % NHEAD;
    const int t = threadIdx.x;
    const float* kb = qkv + (size_t)b * SEQ * QKVDIM + CDIM + h * HDIM;
    const float* vb = qkv + (size_t)b * SEQ * QKVDIM + 2 * CDIM + h * HDIM;
    float2* pkt = pk + ((size_t)z * 32 + j) * 2048;
    float2* pvt = pv + ((size_t)z * 32 + j) * 2048;
#pragma unroll
    for (int i = 0; i < 8; i++) {
        const int it = t + i * 256;
        const int f = it >> 5, lane = it & 31;
        const int nf = f >> 3, ks = f & 7, lr = lane >> 2, lc = lane & 3;
        const float* p = kb + (size_t)(j * 64 + nf * 8 + lr) * QKVDIM + ks * 8 + lc;
        pkt[it] = make_float2(p[0], p[4]);
        const float* q = vb + (size_t)(j * 64 + ks * 8 + lc) * QKVDIM + nf * 8 + lr;
        pvt[it] = make_float2(q[0], q[4 * QKVDIM]);
    }
}

// ---------------- common helpers ----------------
__device__ __forceinline__ void cp16(uint32_t dst, const void* src) {
    asm volatile("cp.async.cg.shared.global [%0], [%1], 16;\n" :: "r"(dst), "l"(src));
}
__device__ __forceinline__ void cp_commit() { asm volatile("cp.async.commit_group;\n"); }

__device__ __forceinline__ void mma8(float* c, const uint32_t* a, const uint32_t* b) {
    asm volatile(
        "mma.sync.aligned.m16n8k8.row.col.f32.tf32.tf32.f32 "
        "{%0,%1,%2,%3}, {%4,%5,%6,%7}, {%8,%9}, {%0,%1,%2,%3};"
        : "+f"(c[0]), "+f"(c[1]), "+f"(c[2]), "+f"(c[3])
        : "r"(a[0]), "r"(a[1]), "r"(a[2]), "r"(a[3]), "r"(b[0]), "r"(b[1]));
}

// swizzled float index within a [rows][32] panel: 16B word c stored at c^(row&7)
__device__ __forceinline__ int swz(int row, int c) {
    return (row << 5) + (((c ^ (row & 7))) << 2);
}

// ---------------- fused flash attention v3 ----------------
// Q panels in smem, K/V packed (linear LDS.64), P via intra-quad shuffles.
// smem floats: Q[2p][128][32] @0 | Kp[2buf][4096] @8192 | Vp[2buf][4096] @16384 = 96KB
// 2 CTAs/SM (regs capped at 128).
__global__ void __launch_bounds__(256, 2)
flash_attn(const float* __restrict__ qkv, const float2* __restrict__ pk,
           const float2* __restrict__ pv, float* __restrict__ attn) {
    extern __shared__ float fsm[];
    const uint32_t sb = (uint32_t)__cvta_generic_to_shared(fsm);

    const int t = threadIdx.x, lane = t & 31, warp = t >> 5;
    const int lr = lane >> 2, lc = lane & 3;
    const int z = blockIdx.y, b = z / NHEAD, h = z % NHEAD;
    const int m0 = blockIdx.x * 128;

    const float* Qg = qkv + (size_t)b * SEQ * QKVDIM + h * HDIM;
    const float2* pkz = pk + (size_t)z * 32 * 2048;
    const float2* pvz = pv + (size_t)z * 32 * 2048;

    // stage Q into swizzled panels
#pragma unroll
    for (int i = 0; i < 8; i++) {
        const int idx = t + i * 256;
        const int p = idx >> 10, w = idx & 1023;
        const int row = w >> 3, c = w & 7;
        cp16(sb + (uint32_t)(p * 4096 + swz(row, c)) * 4u,
             Qg + (size_t)(m0 + row) * QKVDIM + p * 32 + c * 4);
    }
    auto stage = [&](int j) {   // linear copy of packed K & V tiles
        const int buf = j & 1;
        const float4* ks = (const float4*)(pkz + (size_t)j * 2048);
        const uint32_t kd = sb + (uint32_t)(8192 + buf * 4096) * 4u;
#pragma unroll
        for (int i = 0; i < 4; i++) cp16(kd + (t + i * 256) * 16, ks + t + i * 256);
        const float4* vs = (const float4*)(pvz + (size_t)j * 2048);
        const uint32_t vd = sb + (uint32_t)(16384 + buf * 4096) * 4u;
#pragma unroll
        for (int i = 0; i < 4; i++) cp16(vd + (t + i * 256) * 16, vs + t + i * 256);
        cp_commit();
    };
    stage(0);   // group 0 = Q + K0 + V0

    float accO[8][4] = {};
    float m_lo = -1e30f, m_hi = -1e30f, l_lo = 0.f, l_hi = 0.f;
    const int r0 = warp * 16 + lr;
    const int src0 = (lane & 28) | (lc >> 1);   // 4*lr + (lc>>1)
    const int src1 = src0 + 2;
    const bool odd = lc & 1;

    for (int j = 0; j < 32; j++) {
        asm volatile("cp.async.wait_group 0;\n" ::: "memory");
        __syncthreads();
        if (j + 1 < 32) stage(j + 1);   // overlaps compute below

        // ---- S = Q K^T (128x64 tile); Q frags from smem panels ----
        float s[8][4] = {};
        const float2* kp = (const float2*)(fsm + 8192 + (j & 1) * 4096);
#pragma unroll
        for (int ks = 0; ks < 8; ks++) {
            const uint32_t* qp = (const uint32_t*)(fsm + (ks >> 2) * 4096);
            const int k2 = (ks & 3) * 2;
            uint32_t qf[4];
            qf[0] = qp[swz(r0,     k2)     + lc];
            qf[1] = qp[swz(r0 + 8, k2)     + lc];
            qf[2] = qp[swz(r0,     k2 + 1) + lc];
            qf[3] = qp[swz(r0 + 8, k2 + 1) + lc];
#pragma unroll
            for (int nf = 0; nf < 8; nf++) {
                float2 bfv = kp[(nf * 8 + ks) * 32 + lane];
                mma8(s[nf], qf, (const uint32_t*)&bfv);
            }
        }

        // ---- online softmax ----
        float mx_lo = -1e30f, mx_hi = -1e30f;
#pragma unroll
        for (int nf = 0; nf < 8; nf++) {
#pragma unroll
            for (int k4 = 0; k4 < 4; k4++) s[nf][k4] *= 0.125f;
            mx_lo = fmaxf(mx_lo, fmaxf(s[nf][0], s[nf][1]));
            mx_hi = fmaxf(mx_hi, fmaxf(s[nf][2], s[nf][3]));
        }
        mx_lo = fmaxf(mx_lo, __shfl_xor_sync(~0u, mx_lo, 1));
        mx_lo = fmaxf(mx_lo, __shfl_xor_sync(~0u, mx_lo, 2));
        mx_hi = fmaxf(mx_hi, __shfl_xor_sync(~0u, mx_hi, 1));
        mx_hi = fmaxf(mx_hi, __shfl_xor_sync(~0u, mx_hi, 2));
        const float mn_lo = fmaxf(m_lo, mx_lo), mn_hi = fmaxf(m_hi, mx_hi);
        const float al = __expf(m_lo - mn_lo), ah = __expf(m_hi - mn_hi);
        m_lo = mn_lo; m_hi = mn_hi;

        float rs_lo = 0.f, rs_hi = 0.f;
#pragma unroll
        for (int nf = 0; nf < 8; nf++) {
            s[nf][0] = __expf(s[nf][0] - m_lo);
            s[nf][1] = __expf(s[nf][1] - m_lo);
            s[nf][2] = __expf(s[nf][2] - m_hi);
            s[nf][3] = __expf(s[nf][3] - m_hi);
            rs_lo += s[nf][0] + s[nf][1];
            rs_hi += s[nf][2] + s[nf][3];
        }
        rs_lo += __shfl_xor_sync(~0u, rs_lo, 1);
        rs_lo += __shfl_xor_sync(~0u, rs_lo, 2);
        rs_hi += __shfl_xor_sync(~0u, rs_hi, 1);
        rs_hi += __shfl_xor_sync(~0u, rs_hi, 2);
        l_lo = l_lo * al + rs_lo;
        l_hi = l_hi * ah + rs_hi;
#pragma unroll
        for (int nf = 0; nf < 8; nf++) {
            accO[nf][0] *= al; accO[nf][1] *= al;
            accO[nf][2] *= ah; accO[nf][3] *= ah;
        }

        // ---- O += P V, P A-frags via intra-quad shuffles ----
        const float2* vp = (const float2*)(fsm + 16384 + (j & 1) * 4096);
#pragma unroll
        for (int kk = 0; kk < 8; kk++) {
            float a0 = __shfl_sync(~0u, s[kk][0], src0);
            float a1 = __shfl_sync(~0u, s[kk][1], src0);
            float b0 = __shfl_sync(~0u, s[kk][2], src0);
            float b1 = __shfl_sync(~0u, s[kk][3], src0);
            float c0 = __shfl_sync(~0u, s[kk][0], src1);
            float c1 = __shfl_sync(~0u, s[kk][1], src1);
            float d0 = __shfl_sync(~0u, s[kk][2], src1);
            float d1 = __shfl_sync(~0u, s[kk][3], src1);
            float af_[4];
            af_[0] = odd ? a1 : a0;   // P[r0][8kk+lc]
            af_[1] = odd ? b1 : b0;   // P[r0+8][8kk+lc]
            af_[2] = odd ? c1 : c0;   // P[r0][8kk+lc+4]
            af_[3] = odd ? d1 : d0;   // P[r0+8][8kk+lc+4]
#pragma unroll
            for (int nf = 0; nf < 8; nf++) {
                float2 bfv = vp[(nf * 8 + kk) * 32 + lane];
                mma8(accO[nf], (const uint32_t*)af_, (const uint32_t*)&bfv);
            }
        }
    }

    // ---- epilogue ----
    const float inv_lo = 1.0f / l_lo, inv_hi = 1.0f / l_hi;
    float* Cb = attn + (size_t)b * SEQ * CDIM + h * HDIM;
    const int m = m0 + r0;
#pragma unroll
    for (int nf = 0; nf < 8; nf++) {
        const int n = 8 * nf + 2 * lc;
        *(float2*)(Cb + (size_t)m * CDIM + n) =
            make_float2(accO[nf][0] * inv_lo, accO[nf][1] * inv_lo);
        *(float2*)(Cb + (size_t)(m + 8) * CDIM + n) =
            make_float2(accO[nf][2] * inv_hi, accO[nf][3] * inv_hi);
    }
}

// ---------------- TF32 tensor-core NT GEMM, 2-stage cp.async ----------------
template <int EPI, int WARP_M, int WARP_N, int WM_T, int WN_T>
__global__ void __launch_bounds__(WARP_M * WARP_N * 32, 2)
gemm_tc(const float* __restrict__ A, int lda,
        const float* __restrict__ B, int ldb,
        float* __restrict__ C, int ldc, int K,
        const float* __restrict__ bias,
        const float* __restrict__ res) {
    constexpr int NT = WARP_M * WARP_N * 32;
    constexpr int BM = WARP_M * WM_T * 16;
    constexpr int BN = WARP_N * WN_T * 8;
    constexpr int ASZ = BM * 32;
    constexpr int BSZ = BN * 32;
    constexpr int STG = ASZ + BSZ;
    constexpr int NA = ASZ / 4 / NT;
    constexpr int NB = BSZ / 4 / NT;

    extern __shared__ uint32_t smem[];
    const uint32_t smem_b = (uint32_t)__cvta_generic_to_shared(smem);

    const int m0 = blockIdx.y * BM;
    const int n0 = blockIdx.x * BN;
    const int t = threadIdx.x;
    const int lane = t & 31, warp = t >> 5;
    const int wm = warp / WARP_N, wn = warp % WARP_N;
    const int lr = lane >> 2, lc = lane & 3;

    const float* Abase = A + (size_t)m0 * lda;
    const float* Bbase = B + (size_t)n0 * ldb;

    auto issue = [&](int j, int buf) {
        const float* Ak = Abase + j * 32;
        const uint32_t sa = smem_b + (uint32_t)(buf * STG) * 4u;
#pragma unroll
        for (int i = 0; i < NA; i++) {
            const int idx = t + i * NT;
            const int row = idx >> 3, c = idx & 7;
            cp16(sa + (uint32_t)swz(row, c) * 4u, Ak + (size_t)row * lda + c * 4);
        }
        const float* Bk = Bbase + j * 32;
        const uint32_t sbp = smem_b + (uint32_t)(buf * STG + ASZ) * 4u;
#pragma unroll
        for (int i = 0; i < NB; i++) {
            const int idx = t + i * NT;
            const int row = idx >> 3, c = idx & 7;
            cp16(sbp + (uint32_t)swz(row, c) * 4u, Bk + (size_t)row * ldb + c * 4);
        }
        cp_commit();
    };

    const int T = K >> 5;
    issue(0, 0);
    issue(1, 1);

    float acc[WM_T][WN_T][4] = {};
    int buf = 0;

    for (int j = 0; j < T; j++) {
        asm volatile("cp.async.wait_group 1;\n" ::: "memory");
        __syncthreads();
        const uint32_t* a = smem + buf * STG;
        const uint32_t* b = a + ASZ;

#pragma unroll
        for (int ks = 0; ks < 4; ks++) {
            uint32_t af[WM_T][4], bf[WN_T][2];
#pragma unroll
            for (int mt = 0; mt < WM_T; mt++) {
                const int row = (wm * WM_T + mt) * 16 + lr;
                af[mt][0] = a[swz(row,     2 * ks)     + lc];
                af[mt][1] = a[swz(row + 8, 2 * ks)     + lc];
                af[mt][2] = a[swz(row,     2 * ks + 1) + lc];
                af[mt][3] = a[swz(row + 8, 2 * ks + 1) + lc];
            }
#pragma unroll
            for (int nf = 0; nf < WN_T; nf++) {
                const int row = (wn * WN_T + nf) * 8 + lr;
                bf[nf][0] = b[swz(row, 2 * ks)     + lc];
                bf[nf][1] = b[swz(row, 2 * ks + 1) + lc];
            }
#pragma unroll
            for (int mt = 0; mt < WM_T; mt++)
#pragma unroll
                for (int nf = 0; nf < WN_T; nf++)
                    mma8(acc[mt][nf], af[mt], bf[nf]);
        }
        __syncthreads();
        if (j + 2 < T) issue(j + 2, buf);
        else cp_commit();
        buf ^= 1;
    }

#pragma unroll
    for (int mi = 0; mi < WM_T; mi++) {
        const int m = m0 + (wm * WM_T + mi) * 16 + lr;
#pragma unroll
        for (int ni = 0; ni < WN_T; ni++) {
            const int n = n0 + (wn * WN_T + ni) * 8 + (lc << 1);
            float2 bb = make_float2(0.f, 0.f);
            if (EPI != 0) bb = *(const float2*)(bias + n);
#pragma unroll
            for (int half = 0; half < 2; half++) {
                const int mm = m + half * 8;
                float v0 = acc[mi][ni][half * 2 + 0];
                float v1 = acc[mi][ni][half * 2 + 1];
                if (EPI != 0) { v0 += bb.x; v1 += bb.y; }
                if (EPI == 2) {
                    float2 r2 = *(const float2*)(res + (size_t)mm * ldc + n);
                    v0 += r2.x; v1 += r2.y;
                }
                if (EPI == 3) {
                    v0 = 0.5f * v0 * (1.0f + erff(v0 * 0.70710678118654752f));
                    v1 = 0.5f * v1 * (1.0f + erff(v1 * 0.70710678118654752f));
                }
                *(float2*)(C + (size_t)mm * ldc + n) = make_float2(v0, v1);
            }
        }
    }
}

// ---------------- launch ----------------
extern "C" void kernel_launch(void* const* d_in, const int* in_sizes, int n_in,
                              void* d_out, int out_size) {
    const float* x      = (const float*)d_in[0];
    const float* ln1_g  = (const float*)d_in[1];
    const float* ln1_b  = (const float*)d_in[2];
    const float* qkv_w  = (const float*)d_in[3];
    const float* proj_w = (const float*)d_in[4];
    const float* proj_b = (const float*)d_in[5];
    const float* ln2_g  = (const float*)d_in[6];
    const float* ln2_b  = (const float*)d_in[7];
    const float* fc1_w  = (const float*)d_in[8];
    const float* fc1_b  = (const float*)d_in[9];
    const float* fc2_w  = (const float*)d_in[10];
    const float* fc2_b  = (const float*)d_in[11];
    float* out = (float*)d_out;

    float *h, *qkv, *attn, *x1, *fc1;
    float2 *pkp, *pvp;
    cudaGetSymbolAddress((void**)&h, g_h);
    cudaGetSymbolAddress((void**)&qkv, g_qkv);
    cudaGetSymbolAddress((void**)&attn, g_attn);
    cudaGetSymbolAddress((void**)&x1, g_x1);
    cudaGetSymbolAddress((void**)&fc1, g_fc1);
    cudaGetSymbolAddress((void**)&pkp, g_pk);
    cudaGetSymbolAddress((void**)&pvp, g_pv);

    constexpr int SM128 = 2 * (128 * 32 + 128 * 32) * 4;  // 64KB
    constexpr int SMFA  = 24576 * 4;                       // 96KB
    cudaFuncSetAttribute(gemm_tc<0, 2, 4, 4, 4>, cudaFuncAttributeMaxDynamicSharedMemorySize, SM128);
    cudaFuncSetAttribute(gemm_tc<2, 2, 4, 4, 4>, cudaFuncAttributeMaxDynamicSharedMemorySize, SM128);
    cudaFuncSetAttribute(gemm_tc<3, 2, 4, 4, 4>, cudaFuncAttributeMaxDynamicSharedMemorySize, SM128);
    cudaFuncSetAttribute(flash_attn, cudaFuncAttributeMaxDynamicSharedMemorySize, SMFA);

    // 1) LN1
    ln_kernel<<<ROWS, 256>>>(x, ln1_g, ln1_b, h);

    // 2) QKV
    gemm_tc<0, 2, 4, 4, 4><<<dim3(QKVDIM / 128, ROWS / 128, 1), 256, SM128>>>(
        h, CDIM, qkv_w, CDIM, qkv, QKVDIM, CDIM, nullptr, nullptr);

    // 3) pack K/V fragments + fused flash attention
    pack_kv<<<dim3(32, 24), 256>>>(qkv, pkp, pvp);
    flash_attn<<<dim3(SEQ / 128, 24), 256, SMFA>>>(qkv, pkp, pvp, attn);

    // 4) x1 = x + attn @ proj_w^T + proj_b
    gemm_tc<2, 2, 4, 4, 4><<<dim3(CDIM / 128, ROWS / 128, 1), 256, SM128>>>(
        attn, CDIM, proj_w, CDIM, x1, CDIM, CDIM, proj_b, x);

    // 5) LN2
    ln_kernel<<<ROWS, 256>>>(x1, ln2_g, ln2_b, h);

    // 6) fc1 + exact GELU
    gemm_tc<3, 2, 4, 4, 4><<<dim3(HID / 128, ROWS / 128, 1), 256, SM128>>>(
        h, CDIM, fc1_w, CDIM, fc1, HID, CDIM, fc1_b, nullptr);

    // 7) out = x1 + fc1 @ fc2_w^T + fc2_b
    gemm_tc<2, 2, 4, 4, 4><<<dim3(CDIM / 128, ROWS / 128, 1), 256, SM128>>>(
        fc1, HID, fc2_w, HID, out, CDIM, HID, fc2_b, x1);
}

// round 9
// speedup vs baseline: 1.8301x; 1.7041x over previous
#include <cuda_runtime.h>
#include <cuda_fp16.h>
#include <math.h>
#include <stdint.h>

// x: [2, 2048, 768]; heads=12, head_dim=64, mlp=3072
#define ROWS   4096
#define CDIM   768
#define QKVDIM 2304
#define HID    3072
#define NHEAD  12
#define HDIM   64
#define SEQ    2048

// ---------------- scratch ----------------
__device__ __half g_h[ROWS * CDIM];        // LN output (fp16)
__device__ __half g_qkv[ROWS * QKVDIM];    // qkv (fp16)
__device__ __half g_attn[ROWS * CDIM];     // attention out (fp16)
__device__ float  g_x1[ROWS * CDIM];       // residual stream (fp32)
__device__ __half g_fc1[ROWS * HID];       // gelu(fc1) (fp16)
__device__ uint2  g_pk[24 * 32 * 1024];    // packed K frags
__device__ uint2  g_pv[24 * 32 * 1024];    // packed V frags
__device__ uint2  g_pw[1769472];           // packed weights (all 4)

#define PW_QKV  0
#define PW_PROJ 442368
#define PW_FC1  589824
#define PW_FC2  1179648

// ---------------- LayerNorm (fp32 in, fp16 out) ----------------
__global__ void ln_kernel(const float* __restrict__ x, const float* __restrict__ gam,
                          const float* __restrict__ bet, __half* __restrict__ out) {
    __shared__ float red[8];
    const int t = threadIdx.x;
    const float* xr = x + (size_t)blockIdx.x * CDIM;
    __half* orow = out + (size_t)blockIdx.x * CDIM;

    float v0 = xr[t], v1 = xr[t + 256], v2 = xr[t + 512];

    float s = v0 + v1 + v2;
#pragma unroll
    for (int o = 16; o; o >>= 1) s += __shfl_xor_sync(~0u, s, o);
    if ((t & 31) == 0) red[t >> 5] = s;
    __syncthreads();
    s = red[0] + red[1] + red[2] + red[3] + red[4] + red[5] + red[6] + red[7];
    const float mu = s * (1.0f / CDIM);
    __syncthreads();

    float d0 = v0 - mu, d1 = v1 - mu, d2 = v2 - mu;
    float q = d0 * d0 + d1 * d1 + d2 * d2;
#pragma unroll
    for (int o = 16; o; o >>= 1) q += __shfl_xor_sync(~0u, q, o);
    if ((t & 31) == 0) red[t >> 5] = q;
    __syncthreads();
    q = red[0] + red[1] + red[2] + red[3] + red[4] + red[5] + red[6] + red[7];
    const float rs = rsqrtf(q * (1.0f / CDIM) + 1e-5f);

    orow[t]       = __float2half(d0 * rs * gam[t]       + bet[t]);
    orow[t + 256] = __float2half(d1 * rs * gam[t + 256] + bet[t + 256]);
    orow[t + 512] = __float2half(d2 * rs * gam[t + 512] + bet[t + 512]);
}

// ---------------- pack weights: W[N][K] fp32 -> fragment-linear fp16 ----------------
// block = (128 n) x (64 k); frag = nf*4+ks2; lane: b0 = W[8nf+lr][16ks2+2lc..+1], b1 = +8
__global__ void pack_w(const float* __restrict__ W, uint2* __restrict__ pw, int K) {
    const int kt = blockIdx.x, nt = blockIdx.y, nk = gridDim.x;
    uint2* dst = pw + ((size_t)nt * nk + kt) * 2048;
    const float* Wb = W + (size_t)nt * 128 * K + (size_t)kt * 64;
#pragma unroll
    for (int i = 0; i < 8; i++) {
        const int idx = threadIdx.x + i * 256;
        const int nf = idx >> 7, ks2 = (idx >> 5) & 3, lane = idx & 31;
        const int lr = lane >> 2, lc = lane & 3;
        const float* p = Wb + (size_t)(nf * 8 + lr) * K + ks2 * 16 + 2 * lc;
        __half2 b0 = __floats2half2_rn(p[0], p[1]);
        __half2 b1 = __floats2half2_rn(p[8], p[9]);
        dst[idx] = make_uint2(*(uint32_t*)&b0, *(uint32_t*)&b1);
    }
}

// ---------------- pack K,V (fp16 qkv) into fragment layout ----------------
__global__ void pack_kv(const __half* __restrict__ qkv,
                        uint2* __restrict__ pk, uint2* __restrict__ pv) {
    const int z = blockIdx.y, j = blockIdx.x, b = z / NHEAD, h = z % NHEAD;
    const int t = threadIdx.x;
    const __half* kb = qkv + (size_t)b * SEQ * QKVDIM + CDIM + h * HDIM;
    const __half* vb = qkv + (size_t)b * SEQ * QKVDIM + 2 * CDIM + h * HDIM;
    uint2* pkt = pk + ((size_t)z * 32 + j) * 1024;
    uint2* pvt = pv + ((size_t)z * 32 + j) * 1024;
#pragma unroll
    for (int i = 0; i < 4; i++) {
        const int idx = t + i * 256;
        const int frag = idx >> 5, nf = frag >> 2, ks2 = frag & 3;
        const int lane = idx & 31, lr = lane >> 2, lc = lane & 3;
        // K: b0 = K[8nf+lr][16ks2+2lc..+1], b1 = +8  (contiguous half2)
        const __half* p = kb + (size_t)(j * 64 + 8 * nf + lr) * QKVDIM + 16 * ks2 + 2 * lc;
        pkt[idx] = make_uint2(*(const uint32_t*)p, *(const uint32_t*)(p + 8));
        // V: b0 = (V[kv][d], V[kv+1][d]) with kv = j*64+16ks2+2lc, d = 8nf+lr; b1 = kv+8
        const __half* q0 = vb + (size_t)(j * 64 + 16 * ks2 + 2 * lc) * QKVDIM + 8 * nf + lr;
        __half2 v0 = __halves2half2(q0[0], q0[QKVDIM]);
        __half2 v1 = __halves2half2(q0[8 * QKVDIM], q0[9 * QKVDIM]);
        pvt[idx] = make_uint2(*(uint32_t*)&v0, *(uint32_t*)&v1);
    }
}

// ---------------- common helpers ----------------
__device__ __forceinline__ void cp16(uint32_t dst, const void* src) {
    asm volatile("cp.async.cg.shared.global [%0], [%1], 16;\n" :: "r"(dst), "l"(src));
}
__device__ __forceinline__ void cp_commit() { asm volatile("cp.async.commit_group;\n"); }

__device__ __forceinline__ void mmah(float* c, const uint32_t* a, const uint32_t* b) {
    asm volatile(
        "mma.sync.aligned.m16n8k16.row.col.f32.f16.f16.f32 "
        "{%0,%1,%2,%3}, {%4,%5,%6,%7}, {%8,%9}, {%0,%1,%2,%3};"
        : "+f"(c[0]), "+f"(c[1]), "+f"(c[2]), "+f"(c[3])
        : "r"(a[0]), "r"(a[1]), "r"(a[2]), "r"(a[3]), "r"(b[0]), "r"(b[1]));
}
__device__ __forceinline__ uint32_t f22h2(float lo, float hi) {
    uint32_t r;
    asm("cvt.rn.f16x2.f32 %0, %1, %2;" : "=r"(r) : "f"(hi), "f"(lo));
    return r;
}
__device__ __forceinline__ float ex2f(float x) {
    float r; asm("ex2.approx.f32 %0, %1;" : "=f"(r) : "f"(x)); return r;
}

// swizzled half2-word index within a [rows][32 half2] panel (128B rows)
__device__ __forceinline__ int swz(int row, int c) {
    return (row << 5) + (((c ^ (row & 7))) << 2);
}

// ---------------- fused flash attention (fp16 mma) ----------------
// grid (16 qtiles, 24 heads), 256 thr, 2 CTA/SM.
// smem bytes: Q[0,16K) | Kp[16K + buf*8K) | Vp[32K + buf*8K) = 48KB
__global__ void __launch_bounds__(256, 2)
flash_h(const __half* __restrict__ qkv, const uint2* __restrict__ pk,
        const uint2* __restrict__ pv, __half* __restrict__ attn) {
    extern __shared__ float fsm[];
    const uint32_t sb = (uint32_t)__cvta_generic_to_shared(fsm);

    const int t = threadIdx.x, lane = t & 31, warp = t >> 5;
    const int lr = lane >> 2, lc = lane & 3;
    const int z = blockIdx.y, b = z / NHEAD, h = z % NHEAD;
    const int m0 = blockIdx.x * 128;

    const __half* Qg = qkv + (size_t)b * SEQ * QKVDIM + h * HDIM;
    const uint2* pkz = pk + (size_t)z * 32 * 1024;
    const uint2* pvz = pv + (size_t)z * 32 * 1024;

    // stage Q: 128 rows x 64 halves (128B rows, swizzled 16B chunks)
#pragma unroll
    for (int i = 0; i < 4; i++) {
        const int idx = t + i * 256;
        const int row = idx >> 3, c = idx & 7;
        cp16(sb + row * 128 + ((c ^ (row & 7)) << 4),
             Qg + (size_t)(m0 + row) * QKVDIM + c * 8);
    }
    auto stage = [&](int j) {
        const int buf = j & 1;
        const char* ks = (const char*)(pkz + (size_t)j * 1024);
        const char* vs = (const char*)(pvz + (size_t)j * 1024);
#pragma unroll
        for (int i = 0; i < 2; i++) {
            const int idx = t + i * 256;
            cp16(sb + 16384 + buf * 8192 + idx * 16, ks + idx * 16);
            cp16(sb + 32768 + buf * 8192 + idx * 16, vs + idx * 16);
        }
        cp_commit();
    };
    stage(0);   // group 0 = Q + K0 + V0

    float accO[8][4] = {};
    float m_lo = -1e30f, m_hi = -1e30f, l_lo = 0.f, l_hi = 0.f;
    const int r0 = warp * 16 + lr;
    const uint32_t* qp = (const uint32_t*)fsm;
    const float SCL = 0.125f * 1.44269504f;   // head_dim^-0.5 * log2(e)

    for (int j = 0; j < 32; j++) {
        asm volatile("cp.async.wait_group 0;\n" ::: "memory");
        __syncthreads();
        if (j + 1 < 32) stage(j + 1);

        // ---- S = Q K^T (128x64) ----
        float s[8][4] = {};
        const uint2* kp = (const uint2*)((const char*)fsm + 16384 + (j & 1) * 8192);
#pragma unroll
        for (int ks2 = 0; ks2 < 4; ks2++) {
            uint32_t qf[4];
            qf[0] = qp[swz(r0,     2 * ks2)     + lc];
            qf[1] = qp[swz(r0 + 8, 2 * ks2)     + lc];
            qf[2] = qp[swz(r0,     2 * ks2 + 1) + lc];
            qf[3] = qp[swz(r0 + 8, 2 * ks2 + 1) + lc];
#pragma unroll
            for (int nf = 0; nf < 8; nf++) {
                uint2 bf = kp[(nf * 4 + ks2) * 32 + lane];
                mmah(s[nf], qf, (const uint32_t*)&bf);
            }
        }

        // ---- online softmax (base-2; sum deferred to epilogue) ----
        float mx_lo = -1e30f, mx_hi = -1e30f;
#pragma unroll
        for (int nf = 0; nf < 8; nf++) {
#pragma unroll
            for (int k4 = 0; k4 < 4; k4++) s[nf][k4] *= SCL;
            mx_lo = fmaxf(mx_lo, fmaxf(s[nf][0], s[nf][1]));
            mx_hi = fmaxf(mx_hi, fmaxf(s[nf][2], s[nf][3]));
        }
        mx_lo = fmaxf(mx_lo, __shfl_xor_sync(~0u, mx_lo, 1));
        mx_lo = fmaxf(mx_lo, __shfl_xor_sync(~0u, mx_lo, 2));
        mx_hi = fmaxf(mx_hi, __shfl_xor_sync(~0u, mx_hi, 1));
        mx_hi = fmaxf(mx_hi, __shfl_xor_sync(~0u, mx_hi, 2));
        const float mn_lo = fmaxf(m_lo, mx_lo), mn_hi = fmaxf(m_hi, mx_hi);
        const float al = ex2f(m_lo - mn_lo), ah = ex2f(m_hi - mn_hi);
        m_lo = mn_lo; m_hi = mn_hi;

        float sl = 0.f, sh = 0.f;
#pragma unroll
        for (int nf = 0; nf < 8; nf++) {
            s[nf][0] = ex2f(s[nf][0] - m_lo);
            s[nf][1] = ex2f(s[nf][1] - m_lo);
            s[nf][2] = ex2f(s[nf][2] - m_hi);
            s[nf][3] = ex2f(s[nf][3] - m_hi);
            sl += s[nf][0] + s[nf][1];
            sh += s[nf][2] + s[nf][3];
        }
        l_lo = l_lo * al + sl;
        l_hi = l_hi * ah + sh;
#pragma unroll
        for (int nf = 0; nf < 8; nf++) {
            accO[nf][0] *= al; accO[nf][1] *= al;
            accO[nf][2] *= ah; accO[nf][3] *= ah;
        }

        // ---- O += P V ; P A-frags = per-lane cvt of S C-frags ----
        const uint2* vp = (const uint2*)((const char*)fsm + 32768 + (j & 1) * 8192);
#pragma unroll
        for (int ks2 = 0; ks2 < 4; ks2++) {
            uint32_t af[4];
            af[0] = f22h2(s[2 * ks2][0],     s[2 * ks2][1]);
            af[1] = f22h2(s[2 * ks2][2],     s[2 * ks2][3]);
            af[2] = f22h2(s[2 * ks2 + 1][0], s[2 * ks2 + 1][1]);
            af[3] = f22h2(s[2 * ks2 + 1][2], s[2 * ks2 + 1][3]);
#pragma unroll
            for (int nf = 0; nf < 8; nf++) {
                uint2 bf = vp[(nf * 4 + ks2) * 32 + lane];
                mmah(accO[nf], af, (const uint32_t*)&bf);
            }
        }
    }

    // ---- epilogue: finish quad sum, normalize, store fp16 ----
    l_lo += __shfl_xor_sync(~0u, l_lo, 1);
    l_lo += __shfl_xor_sync(~0u, l_lo, 2);
    l_hi += __shfl_xor_sync(~0u, l_hi, 1);
    l_hi += __shfl_xor_sync(~0u, l_hi, 2);
    const float inv_lo = 1.0f / l_lo, inv_hi = 1.0f / l_hi;
    __half* Cb = attn + (size_t)b * SEQ * CDIM + h * HDIM;
    const int m = m0 + r0;
#pragma unroll
    for (int nf = 0; nf < 8; nf++) {
        const int n = 8 * nf + 2 * lc;
        __half2 v0 = __floats2half2_rn(accO[nf][0] * inv_lo, accO[nf][1] * inv_lo);
        __half2 v1 = __floats2half2_rn(accO[nf][2] * inv_hi, accO[nf][3] * inv_hi);
        *(__half2*)(Cb + (size_t)m * CDIM + n) = v0;
        *(__half2*)(Cb + (size_t)(m + 8) * CDIM + n) = v1;
    }
}

// ---------------- fp16 tensor-core NT GEMM ----------------
// C[M,N] = A[M,K] @ W[N,K]^T (+epilogue). BM=128, BN=128, BK=64.
// A fp16 swizzled panels; W pre-packed fragment-linear.
// EPI: 0 = none -> half out; 2 = +bias+res -> float out; 3 = gelu(+bias) -> half out
template <int EPI>
__global__ void __launch_bounds__(256, 2)
gemm_h(const __half* __restrict__ A, int lda, const uint2* __restrict__ PW,
       void* __restrict__ C, int ldc, int K,
       const float* __restrict__ bias, const float* __restrict__ res) {
    extern __shared__ uint32_t smem[];
    const uint32_t smem_b = (uint32_t)__cvta_generic_to_shared(smem);

    const int m0 = blockIdx.y * 128;
    const int n0 = blockIdx.x * 128;
    const int t = threadIdx.x;
    const int lane = t & 31, warp = t >> 5;
    const int wm = warp >> 2, wn = warp & 3;
    const int lr = lane >> 2, lc = lane & 3;

    const __half* Abase = A + (size_t)m0 * lda;
    const uint2* pwbase = PW + (size_t)(n0 >> 7) * (K >> 6) * 2048;

    auto issue = [&](int j, int buf) {
        // A tile: 128 rows x 64 halves, swizzled
        const __half* Ak = Abase + j * 64;
#pragma unroll
        for (int i = 0; i < 4; i++) {
            const int idx = t + i * 256;
            const int row = idx >> 3, c = idx & 7;
            cp16(smem_b + buf * 32768 + row * 128 + ((c ^ (row & 7)) << 4),
                 Ak + (size_t)row * lda + c * 8);
        }
        // B tile: 16KB linear
        const char* Bk = (const char*)(pwbase + (size_t)j * 2048);
#pragma unroll
        for (int i = 0; i < 4; i++) {
            const int idx = t + i * 256;
            cp16(smem_b + buf * 32768 + 16384 + idx * 16, Bk + idx * 16);
        }
        cp_commit();
    };

    const int T = K >> 6;
    issue(0, 0);
    issue(1, 1);

    float acc[4][4][4] = {};
    int buf = 0;

    for (int j = 0; j < T; j++) {
        asm volatile("cp.async.wait_group 1;\n" ::: "memory");
        __syncthreads();
        const uint32_t* a = smem + buf * 8192;
        const uint2* bp = (const uint2*)(smem + buf * 8192 + 4096);

#pragma unroll
        for (int ks2 = 0; ks2 < 4; ks2++) {
            uint32_t af[4][4];
            uint2 bf[4];
#pragma unroll
            for (int mt = 0; mt < 4; mt++) {
                const int row = (wm * 4 + mt) * 16 + lr;
                af[mt][0] = a[swz(row,     2 * ks2)     + lc];
                af[mt][1] = a[swz(row + 8, 2 * ks2)     + lc];
                af[mt][2] = a[swz(row,     2 * ks2 + 1) + lc];
                af[mt][3] = a[swz(row + 8, 2 * ks2 + 1) + lc];
            }
#pragma unroll
            for (int nf = 0; nf < 4; nf++)
                bf[nf] = bp[((wn * 4 + nf) * 4 + ks2) * 32 + lane];
#pragma unroll
            for (int mt = 0; mt < 4; mt++)
#pragma unroll
                for (int nf = 0; nf < 4; nf++)
                    mmah(acc[mt][nf], af[mt], (const uint32_t*)&bf[nf]);
        }
        __syncthreads();
        if (j + 2 < T) issue(j + 2, buf);
        else cp_commit();
        buf ^= 1;
    }

    // ---- epilogue ----
#pragma unroll
    for (int mi = 0; mi < 4; mi++) {
        const int m = m0 + (wm * 4 + mi) * 16 + lr;
#pragma unroll
        for (int ni = 0; ni < 4; ni++) {
            const int n = n0 + (wn * 4 + ni) * 8 + (lc << 1);
            float2 bb = make_float2(0.f, 0.f);
            if (EPI != 0) bb = *(const float2*)(bias + n);
#pragma unroll
            for (int hf = 0; hf < 2; hf++) {
                const int mm = m + hf * 8;
                float v0 = acc[mi][ni][hf * 2 + 0];
                float v1 = acc[mi][ni][hf * 2 + 1];
                if (EPI != 0) { v0 += bb.x; v1 += bb.y; }
                if (EPI == 2) {
                    float2 r2 = *(const float2*)(res + (size_t)mm * ldc + n);
                    v0 += r2.x; v1 += r2.y;
                    *(float2*)((float*)C + (size_t)mm * ldc + n) = make_float2(v0, v1);
                } else if (EPI == 3) {
                    v0 = 0.5f * v0 * (1.0f + erff(v0 * 0.70710678118654752f));
                    v1 = 0.5f * v1 * (1.0f + erff(v1 * 0.70710678118654752f));
                    *(__half2*)((__half*)C + (size_t)mm * ldc + n) = __floats2half2_rn(v0, v1);
                } else {
                    *(__half2*)((__half*)C + (size_t)mm * ldc + n) = __floats2half2_rn(v0, v1);
                }
            }
        }
    }
}

// ---------------- launch ----------------
extern "C" void kernel_launch(void* const* d_in, const int* in_sizes, int n_in,
                              void* d_out, int out_size) {
    const float* x      = (const float*)d_in[0];
    const float* ln1_g  = (const float*)d_in[1];
    const float* ln1_b  = (const float*)d_in[2];
    const float* qkv_w  = (const float*)d_in[3];
    const float* proj_w = (const float*)d_in[4];
    const float* proj_b = (const float*)d_in[5];
    const float* ln2_g  = (const float*)d_in[6];
    const float* ln2_b  = (const float*)d_in[7];
    const float* fc1_w  = (const float*)d_in[8];
    const float* fc1_b  = (const float*)d_in[9];
    const float* fc2_w  = (const float*)d_in[10];
    const float* fc2_b  = (const float*)d_in[11];
    float* out = (float*)d_out;

    __half *h, *qkv, *attn, *fc1;
    float* x1;
    uint2 *pkp, *pvp, *pw;
    cudaGetSymbolAddress((void**)&h, g_h);
    cudaGetSymbolAddress((void**)&qkv, g_qkv);
    cudaGetSymbolAddress((void**)&attn, g_attn);
    cudaGetSymbolAddress((void**)&x1, g_x1);
    cudaGetSymbolAddress((void**)&fc1, g_fc1);
    cudaGetSymbolAddress((void**)&pkp, g_pk);
    cudaGetSymbolAddress((void**)&pvp, g_pv);
    cudaGetSymbolAddress((void**)&pw, g_pw);

    constexpr int SMG = 65536;   // 2 stages x (16KB A + 16KB B)
    constexpr int SMF = 49152;   // Q 16KB + K 2x8KB + V 2x8KB
    cudaFuncSetAttribute(gemm_h<0>, cudaFuncAttributeMaxDynamicSharedMemorySize, SMG);
    cudaFuncSetAttribute(gemm_h<2>, cudaFuncAttributeMaxDynamicSharedMemorySize, SMG);
    cudaFuncSetAttribute(gemm_h<3>, cudaFuncAttributeMaxDynamicSharedMemorySize, SMG);
    cudaFuncSetAttribute(flash_h, cudaFuncAttributeMaxDynamicSharedMemorySize, SMF);

    // 0) pack weights (depend only on inputs)
    pack_w<<<dim3(12, 18), 256>>>(qkv_w,  pw + PW_QKV,  CDIM);
    pack_w<<<dim3(12, 6),  256>>>(proj_w, pw + PW_PROJ, CDIM);
    pack_w<<<dim3(12, 24), 256>>>(fc1_w,  pw + PW_FC1,  CDIM);
    pack_w<<<dim3(48, 6),  256>>>(fc2_w,  pw + PW_FC2,  HID);

    // 1) LN1 -> h (fp16)
    ln_kernel<<<ROWS, 256>>>(x, ln1_g, ln1_b, h);

    // 2) QKV (fp16 out)
    gemm_h<0><<<dim3(QKVDIM / 128, ROWS / 128), 256, SMG>>>(
        h, CDIM, pw + PW_QKV, qkv, QKVDIM, CDIM, nullptr, nullptr);

    // 3) pack K/V + flash attention
    pack_kv<<<dim3(32, 24), 256>>>(qkv, pkp, pvp);
    flash_h<<<dim3(SEQ / 128, 24), 256, SMF>>>(qkv, pkp, pvp, attn);

    // 4) x1 = x + attn @ proj_w^T + proj_b (fp32 out)
    gemm_h<2><<<dim3(CDIM / 128, ROWS / 128), 256, SMG>>>(
        attn, CDIM, pw + PW_PROJ, x1, CDIM, CDIM, proj_b, x);

    // 5) LN2 -> h (fp16)
    ln_kernel<<<ROWS, 256>>>(x1, ln2_g, ln2_b, h);

    // 6) fc1 + exact GELU (fp16 out)
    gemm_h<3><<<dim3(HID / 128, ROWS / 128), 256, SMG>>>(
        h, CDIM, pw + PW_FC1, fc1, HID, CDIM, fc1_b, nullptr);

    // 7) out = x1 + fc1 @ fc2_w^T + fc2_b (fp32 out)
    gemm_h<2><<<dim3(CDIM / 128, ROWS / 128), 256, SMG>>>(
        fc1, HID, pw + PW_FC2, out, CDIM, HID, fc2_b, x1);
}